// round 2
// baseline (speedup 1.0000x reference)
#include <cuda_runtime.h>
#include <math.h>

#define NN 100000
#define NE 1600000
#define ESL (NE + NN)
#define NGRAPH 64
#define NEG 0.2f

// ---------------- scratch (device globals; no allocation) ----------------
__device__ float    d_cnt[NN];
__device__ float    d_mean[NN * 8];
__device__ float    d_xp[NN * 64];
__device__ float    d_als[NN * 4];
__device__ float    d_ald[NN * 4];
__device__ float    d_alpha[(size_t)ESL * 4];   // CSR-permuted order
__device__ unsigned d_m[NN * 4];
__device__ float    d_den_unused[4];
__device__ float    d_h0[NN * 64];
__device__ float    d_h1[NN * 64];
__device__ float    d_pool[NGRAPH * 64];
__device__ float    d_gcnt[NGRAPH];
__device__ float    d_weatt[32];
// CSR
__device__ int      d_roff[NN + 1];
__device__ int      d_cur[NN];
__device__ int      d_csrc[ESL];   // src node per CSR slot
__device__ int      d_poe[ESL];    // edge -> CSR slot

// ---------------- helpers ----------------
__device__ __forceinline__ unsigned fenc(float f) {
    unsigned u = __float_as_uint(f);
    return (u & 0x80000000u) ? ~u : (u | 0x80000000u);
}
__device__ __forceinline__ float fdec(unsigned u) {
    return (u & 0x80000000u) ? __uint_as_float(u & 0x7fffffffu) : __uint_as_float(~u);
}
__device__ __forceinline__ void red2(float* p, float a, float b) {
    asm volatile("red.global.add.v2.f32 [%0], {%1, %2};" :: "l"(p), "f"(a), "f"(b) : "memory");
}

// ---------------- self-loop mean edge-attr + in-degree count ----------------
__global__ void k_count(const int* __restrict__ dst, const float* __restrict__ ea) {
    int e = blockIdx.x * blockDim.x + threadIdx.x;
    if (e >= NE) return;
    int dd = dst[e];
    atomicAdd(&d_cnt[dd], 1.0f);
#pragma unroll
    for (int d = 0; d < 8; d += 2)
        red2(&d_mean[dd * 8 + d], ea[(size_t)e * 8 + d], ea[(size_t)e * 8 + d + 1]);
}

__global__ void k_meandiv() {
    int i = blockIdx.x * blockDim.x + threadIdx.x;
    if (i >= NN * 8) return;
    d_mean[i] = d_mean[i] / fmaxf(d_cnt[i >> 3], 1.0f);
}

// ---------------- CSR offsets: deg[n] = cnt[n] + 1 (self loop); exclusive scan ----------------
__global__ void k_scan() {
    __shared__ int ssum[1024];
    const int CH = (NN + 1023) / 1024;
    int t = threadIdx.x;
    int base = t * CH;
    int s = 0;
    for (int i = 0; i < CH; i++) {
        int idx = base + i;
        if (idx < NN) s += (int)(d_cnt[idx] + 0.5f) + 1;
    }
    ssum[t] = s;
    __syncthreads();
    for (int off = 1; off < 1024; off <<= 1) {
        int v = (t >= off) ? ssum[t - off] : 0;
        __syncthreads();
        ssum[t] += v;
        __syncthreads();
    }
    int run = (t == 0) ? 0 : ssum[t - 1];
    for (int i = 0; i < CH; i++) {
        int idx = base + i;
        if (idx < NN) {
            d_roff[idx] = run;
            d_cur[idx] = run;
            run += (int)(d_cnt[idx] + 0.5f) + 1;
        }
    }
    if (t == 1023) d_roff[NN] = ESL;
}

// ---------------- CSR fill ----------------
__global__ void k_fill(const int* __restrict__ src, const int* __restrict__ dst) {
    int e = blockIdx.x * blockDim.x + threadIdx.x;
    if (e >= ESL) return;
    int s, dd;
    if (e < NE) { s = src[e]; dd = dst[e]; } else { s = dd = e - NE; }
    int pos = atomicAdd(&d_cur[dd], 1);
    d_csrc[pos] = s;
    d_poe[e] = pos;
}

// ---------------- per-layer edge-attention weight: weatt[d][h] ----------------
__global__ void k_weatt(const float* __restrict__ We, const float* __restrict__ ae) {
    int t = threadIdx.x;
    if (t >= 32) return;
    int d = t >> 2, h = t & 3;
    float s = 0.0f;
#pragma unroll
    for (int c = 0; c < 16; c++) s += We[d * 64 + h * 16 + c] * ae[h * 16 + c];
    d_weatt[d * 4 + h] = s;
}

// ---------------- projection: xp = X @ W ; al_s/al_d per (node, head) ----------------
__global__ void k_project(const float* __restrict__ X, int fin, const float* __restrict__ W,
                          const float* __restrict__ as_, const float* __restrict__ ad_) {
    __shared__ float sW[64 * 64];
    __shared__ float sx[4 * 64];
    __shared__ float sa[64], sd[64];
    int tid = threadIdx.x;
    for (int i = tid; i < fin * 64; i += 256) sW[i] = W[i];
    if (tid < 64) { sa[tid] = as_[tid]; sd[tid] = ad_[tid]; }
    __syncthreads();
    int slot = tid >> 6, col = tid & 63;
    for (int base = blockIdx.x * 4; base < NN; base += gridDim.x * 4) {
        int n = base + slot;
        if (n < NN && col < fin) sx[slot * 64 + col] = X[(size_t)n * fin + col];
        __syncthreads();
        if (n < NN) {
            float acc = 0.0f;
#pragma unroll 4
            for (int i = 0; i < fin; i += 4) {
                float4 xv = *(const float4*)(sx + slot * 64 + i);
                acc += xv.x * sW[(i + 0) * 64 + col];
                acc += xv.y * sW[(i + 1) * 64 + col];
                acc += xv.z * sW[(i + 2) * 64 + col];
                acc += xv.w * sW[(i + 3) * 64 + col];
            }
            d_xp[(size_t)n * 64 + col] = acc;
            float ps = acc * sa[col], pd = acc * sd[col];
#pragma unroll
            for (int off = 8; off; off >>= 1) {
                ps += __shfl_xor_sync(0xffffffffu, ps, off);
                pd += __shfl_xor_sync(0xffffffffu, pd, off);
            }
            if ((col & 15) == 0) {
                int h = col >> 4;
                d_als[n * 4 + h] = ps;
                d_ald[n * 4 + h] = pd;
            }
        }
        __syncthreads();
    }
}

// ---------------- alpha (leaky-relu logits) -> CSR-permuted store + segment max ----------------
__global__ void k_alpha(const int* __restrict__ src, const int* __restrict__ dst,
                        const float* __restrict__ ea) {
    __shared__ float sw[32];
    if (threadIdx.x < 32) sw[threadIdx.x] = d_weatt[threadIdx.x];
    __syncthreads();
    int e = blockIdx.x * blockDim.x + threadIdx.x;
    if (e >= ESL) return;
    int s, dd;
    const float* a;
    if (e < NE) { s = src[e]; dd = dst[e]; a = ea + (size_t)e * 8; }
    else        { s = dd = e - NE;         a = d_mean + (size_t)(e - NE) * 8; }
    float ale[4] = {0.f, 0.f, 0.f, 0.f};
#pragma unroll
    for (int d = 0; d < 8; d++) {
        float v = a[d];
#pragma unroll
        for (int h = 0; h < 4; h++) ale[h] += v * sw[d * 4 + h];
    }
    int pos = d_poe[e];
    float4 out;
    float* po = (float*)&out;
#pragma unroll
    for (int h = 0; h < 4; h++) {
        float al = d_als[s * 4 + h] + d_ald[dd * 4 + h] + ale[h];
        al = al > 0.0f ? al : NEG * al;
        po[h] = al;
        atomicMax(&d_m[dd * 4 + h], fenc(al));
    }
    *(float4*)(d_alpha + (size_t)pos * 4) = out;
}

// ---------------- fused softmax + aggregate + bias (+relu): warp per dst node ----------------
__global__ void k_agg(const float* __restrict__ b, int dorelu, float* __restrict__ out) {
    int warp = (blockIdx.x * blockDim.x + threadIdx.x) >> 5;
    int lane = threadIdx.x & 31;
    if (warp >= NN) return;
    int beg = d_roff[warp];
    int end = d_roff[warp + 1];
    int h = lane >> 3;     // this lane's head (owns cols [2*lane, 2*lane+1])
    int sub = lane & 7;    // edge slot within a batch of 8
    float mx = fdec(d_m[warp * 4 + h]);

    float den = 0.0f, a0 = 0.0f, a1 = 0.0f;
    for (int p0 = beg; p0 < end; p0 += 8) {
        int myp = p0 + sub;
        // each lane computes one distinct (edge, head) coef: edge=sub, head=h
        float c = 0.0f;
        int s = 0;
        if (myp < end) {
            c = __expf(d_alpha[(size_t)myp * 4 + h] - mx);
            s = d_csrc[myp];
        }
        int nb = min(8, end - p0);
#pragma unroll 4
        for (int j = 0; j < nb; j++) {
            float cj = __shfl_sync(0xffffffffu, c, h * 8 + j);
            int   sj = __shfl_sync(0xffffffffu, s, j);
            float2 v = *(const float2*)(d_xp + (size_t)sj * 64 + lane * 2);
            den += cj;
            a0 += cj * v.x;
            a1 += cj * v.y;
        }
    }
    float inv = 1.0f / (den + 1e-16f);
    float o0 = a0 * inv + b[lane * 2];
    float o1 = a1 * inv + b[lane * 2 + 1];
    if (dorelu) { o0 = fmaxf(o0, 0.0f); o1 = fmaxf(o1, 0.0f); }
    *(float2*)(out + (size_t)warp * 64 + lane * 2) = make_float2(o0, o1);
}

// ---------------- global mean pool ----------------
__global__ void k_pool(const int* __restrict__ batch, const float* __restrict__ h) {
    size_t t = (size_t)blockIdx.x * blockDim.x + threadIdx.x;
    int n = (int)(t >> 5);
    if (n >= NN) return;
    int c2 = (int)(t & 31) * 2;
    int g = batch[n];
    red2(&d_pool[g * 64 + c2], h[(size_t)n * 64 + c2], h[(size_t)n * 64 + c2 + 1]);
    if (c2 == 0) atomicAdd(&d_gcnt[g], 1.0f);
}

// ---------------- MLP head ----------------
__global__ void k_mlp(const float* __restrict__ fc1w, const float* __restrict__ fc1b,
                      const float* __restrict__ fc2w, const float* __restrict__ fc2b,
                      float* __restrict__ out) {
    int g = threadIdx.x;
    if (g >= NGRAPH) return;
    float ic = 1.0f / fmaxf(d_gcnt[g], 1.0f);
    float hr[64];
#pragma unroll
    for (int c = 0; c < 64; c++) hr[c] = d_pool[g * 64 + c] * ic;
    float y1[32];
#pragma unroll
    for (int j = 0; j < 32; j++) {
        float s = fc1b[j];
#pragma unroll
        for (int c = 0; c < 64; c++) s += hr[c] * fc1w[c * 32 + j];
        y1[j] = fmaxf(s, 0.0f);
    }
#pragma unroll
    for (int o = 0; o < 2; o++) {
        float s = fc2b[o];
#pragma unroll
        for (int j = 0; j < 32; j++) s += y1[j] * fc2w[j * 2 + o];
        out[g * 2 + o] = s;
    }
}

// ---------------- host ----------------
extern "C" void kernel_launch(void* const* d_in, const int* in_sizes, int n_in,
                              void* d_out, int out_size) {
    (void)in_sizes; (void)n_in; (void)out_size;
    const float* x    = (const float*)d_in[0];
    const int*   ei   = (const int*)d_in[1];
    const float* ea   = (const float*)d_in[2];
    const int*   batch= (const int*)d_in[3];
    const float* W0   = (const float*)d_in[4];
    const float* as0  = (const float*)d_in[5];
    const float* ad0  = (const float*)d_in[6];
    const float* We0  = (const float*)d_in[7];
    const float* ae0  = (const float*)d_in[8];
    const float* b0   = (const float*)d_in[9];
    const float* Wh   = (const float*)d_in[10];
    const float* ash  = (const float*)d_in[11];
    const float* adh  = (const float*)d_in[12];
    const float* Weh  = (const float*)d_in[13];
    const float* aeh  = (const float*)d_in[14];
    const float* bh   = (const float*)d_in[15];
    const float* fc1w = (const float*)d_in[16];
    const float* fc1b = (const float*)d_in[17];
    const float* fc2w = (const float*)d_in[18];
    const float* fc2b = (const float*)d_in[19];
    float* out = (float*)d_out;

    const int* src = ei;
    const int* dst = ei + NE;

    void *p_cnt, *p_mean, *p_m, *p_h0, *p_h1, *p_pool, *p_gcnt;
    cudaGetSymbolAddress(&p_cnt,  d_cnt);
    cudaGetSymbolAddress(&p_mean, d_mean);
    cudaGetSymbolAddress(&p_m,    d_m);
    cudaGetSymbolAddress(&p_h0,   d_h0);
    cudaGetSymbolAddress(&p_h1,   d_h1);
    cudaGetSymbolAddress(&p_pool, d_pool);
    cudaGetSymbolAddress(&p_gcnt, d_gcnt);

    // setup: degree count + self-loop mean attrs + CSR build (shared across layers)
    cudaMemsetAsync(p_cnt, 0, NN * sizeof(float));
    cudaMemsetAsync(p_mean, 0, NN * 8 * sizeof(float));
    k_count<<<(NE + 255) / 256, 256>>>(dst, ea);
    k_meandiv<<<(NN * 8 + 255) / 256, 256>>>();
    k_scan<<<1, 1024>>>();
    k_fill<<<(ESL + 255) / 256, 256>>>(src, dst);

    struct LayerCfg {
        const float* X; int fin; const float* W;
        const float* as; const float* ad; const float* We; const float* ae;
        const float* b; float* hout; int relu;
    };
    LayerCfg L[3] = {
        { x,            32, W0,        as0,      ad0,      We0,       ae0,      b0,      (float*)p_h0, 1 },
        { (float*)p_h0, 64, Wh,        ash,      adh,      Weh,       aeh,      bh,      (float*)p_h1, 0 },
        { (float*)p_h1, 64, Wh + 4096, ash + 64, adh + 64, Weh + 512, aeh + 64, bh + 64, (float*)p_h0, 0 },
    };

    const int gridE = (ESL + 255) / 256;
    for (int l = 0; l < 3; l++) {
        cudaMemsetAsync(p_m, 0, NN * 4 * sizeof(unsigned));
        k_weatt<<<1, 32>>>(L[l].We, L[l].ae);
        k_project<<<1184, 256>>>(L[l].X, L[l].fin, L[l].W, L[l].as, L[l].ad);
        k_alpha<<<gridE, 256>>>(src, dst, ea);
        k_agg<<<(NN * 32 + 255) / 256, 256>>>(L[l].b, L[l].relu, L[l].hout);
    }

    cudaMemsetAsync(p_pool, 0, NGRAPH * 64 * sizeof(float));
    cudaMemsetAsync(p_gcnt, 0, NGRAPH * sizeof(float));
    k_pool<<<(int)(((size_t)NN * 32 + 255) / 256), 256>>>(batch, (const float*)p_h0);
    k_mlp<<<1, 64>>>(fc1w, fc1b, fc2w, fc2b, out);
}

// round 3
// speedup vs baseline: 1.7221x; 1.7221x over previous
#include <cuda_runtime.h>
#include <math.h>

#define NN 100000
#define NE 1600000
#define ESL (NE + NN)
#define NGRAPH 64
#define NEG 0.2f

// ---------------- scratch (device globals; no allocation) ----------------
__device__ float    d_cnt[NN];
__device__ float    d_mean[NN * 8];
__device__ float    d_xp[NN * 64];
__device__ float    d_als[NN * 4];
__device__ float    d_ald[NN * 4];
__device__ float    d_alpha[(size_t)ESL * 4];   // CSR order, coalesced
__device__ float    d_h0[NN * 64];
__device__ float    d_h1[NN * 64];
__device__ float    d_pool[NGRAPH * 64];
__device__ float    d_gcnt[NGRAPH];
__device__ float    d_weatt[3 * 32];            // all 3 layers precomputed
// CSR
__device__ int      d_roff[NN + 1];
__device__ int      d_cur[NN];
__device__ int      d_csrc[ESL];                // src node per CSR slot
__device__ float    d_ea_csr[(size_t)ESL * 8];  // edge attrs in CSR order

// ---------------- helpers ----------------
__device__ __forceinline__ void red2(float* p, float a, float b) {
    asm volatile("red.global.add.v2.f32 [%0], {%1, %2};" :: "l"(p), "f"(a), "f"(b) : "memory");
}

// ---------------- self-loop mean edge-attr + in-degree count ----------------
__global__ void k_count(const int* __restrict__ dst, const float* __restrict__ ea) {
    int e = blockIdx.x * blockDim.x + threadIdx.x;
    if (e >= NE) return;
    int dd = dst[e];
    atomicAdd(&d_cnt[dd], 1.0f);
#pragma unroll
    for (int d = 0; d < 8; d += 2)
        red2(&d_mean[dd * 8 + d], ea[(size_t)e * 8 + d], ea[(size_t)e * 8 + d + 1]);
}

__global__ void k_meandiv() {
    int i = blockIdx.x * blockDim.x + threadIdx.x;
    if (i >= NN * 8) return;
    d_mean[i] = d_mean[i] / fmaxf(d_cnt[i >> 3], 1.0f);
}

// ---------------- CSR offsets: deg[n] = cnt[n] + 1 (self loop); exclusive scan ----------------
__global__ void k_scan() {
    __shared__ int ssum[1024];
    const int CH = (NN + 1023) / 1024;
    int t = threadIdx.x;
    int base = t * CH;
    int s = 0;
    for (int i = 0; i < CH; i++) {
        int idx = base + i;
        if (idx < NN) s += (int)(d_cnt[idx] + 0.5f) + 1;
    }
    ssum[t] = s;
    __syncthreads();
    for (int off = 1; off < 1024; off <<= 1) {
        int v = (t >= off) ? ssum[t - off] : 0;
        __syncthreads();
        ssum[t] += v;
        __syncthreads();
    }
    int run = (t == 0) ? 0 : ssum[t - 1];
    for (int i = 0; i < CH; i++) {
        int idx = base + i;
        if (idx < NN) {
            d_roff[idx] = run;
            d_cur[idx] = run;
            run += (int)(d_cnt[idx] + 0.5f) + 1;
        }
    }
    if (t == 1023) d_roff[NN] = ESL;
}

// ---------------- CSR fill: src ids + permuted edge attrs ----------------
__global__ void k_fill(const int* __restrict__ src, const int* __restrict__ dst,
                       const float* __restrict__ ea) {
    int e = blockIdx.x * blockDim.x + threadIdx.x;
    if (e >= ESL) return;
    int s, dd;
    const float4* a;
    if (e < NE) { s = src[e]; dd = dst[e]; a = (const float4*)(ea + (size_t)e * 8); }
    else        { s = dd = e - NE;         a = (const float4*)(d_mean + (size_t)(e - NE) * 8); }
    float4 a0 = a[0], a1 = a[1];
    int pos = atomicAdd(&d_cur[dd], 1);
    d_csrc[pos] = s;
    float4* o = (float4*)(d_ea_csr + (size_t)pos * 8);
    o[0] = a0; o[1] = a1;
}

// ---------------- all-layer edge-attention weights: weatt[l][d][h] ----------------
__global__ void k_weatt(const float* __restrict__ We0, const float* __restrict__ ae0,
                        const float* __restrict__ Weh, const float* __restrict__ aeh) {
    int t = threadIdx.x;
    if (t >= 96) return;
    int l = t >> 5, r = t & 31;
    int d = r >> 2, h = r & 3;
    const float* We = (l == 0) ? We0 : (Weh + (l - 1) * 512);
    const float* ae = (l == 0) ? ae0 : (aeh + (l - 1) * 64);
    float s = 0.0f;
#pragma unroll
    for (int c = 0; c < 16; c++) s += We[d * 64 + h * 16 + c] * ae[h * 16 + c];
    d_weatt[l * 32 + d * 4 + h] = s;
}

// ---------------- projection: xp = X @ W ; al_s/al_d per (node, head) ----------------
__global__ void k_project(const float* __restrict__ X, int fin, const float* __restrict__ W,
                          const float* __restrict__ as_, const float* __restrict__ ad_) {
    __shared__ float sW[64 * 64];
    __shared__ float sx[4 * 64];
    __shared__ float sa[64], sd[64];
    int tid = threadIdx.x;
    for (int i = tid; i < fin * 64; i += 256) sW[i] = W[i];
    if (tid < 64) { sa[tid] = as_[tid]; sd[tid] = ad_[tid]; }
    __syncthreads();
    int slot = tid >> 6, col = tid & 63;
    for (int base = blockIdx.x * 4; base < NN; base += gridDim.x * 4) {
        int n = base + slot;
        if (n < NN && col < fin) sx[slot * 64 + col] = X[(size_t)n * fin + col];
        __syncthreads();
        if (n < NN) {
            float acc = 0.0f;
#pragma unroll 4
            for (int i = 0; i < fin; i += 4) {
                float4 xv = *(const float4*)(sx + slot * 64 + i);
                acc += xv.x * sW[(i + 0) * 64 + col];
                acc += xv.y * sW[(i + 1) * 64 + col];
                acc += xv.z * sW[(i + 2) * 64 + col];
                acc += xv.w * sW[(i + 3) * 64 + col];
            }
            d_xp[(size_t)n * 64 + col] = acc;
            float ps = acc * sa[col], pd = acc * sd[col];
#pragma unroll
            for (int off = 8; off; off >>= 1) {
                ps += __shfl_xor_sync(0xffffffffu, ps, off);
                pd += __shfl_xor_sync(0xffffffffu, pd, off);
            }
            if ((col & 15) == 0) {
                int h = col >> 4;
                d_als[n * 4 + h] = ps;
                d_ald[n * 4 + h] = pd;
            }
        }
        __syncthreads();
    }
}

// ---------------- fully fused: logits + leaky-relu + segment max + softmax + aggregate + bias
// warp per dst node. lane = h*8 + sub: head h owns output cols [2*lane, 2*lane+1].
__global__ void k_agg(const float* __restrict__ weatt, const float* __restrict__ b,
                      int dorelu, float* __restrict__ out) {
    __shared__ float sw[32];
    int tid = threadIdx.x;
    if (tid < 32) sw[tid] = weatt[tid];
    __syncthreads();
    int warp = (blockIdx.x * blockDim.x + tid) >> 5;
    if (warp >= NN) return;
    int lane = tid & 31;
    int h = lane >> 3, sub = lane & 7;
    int beg = d_roff[warp];
    int end = d_roff[warp + 1];
    float ald_h = d_ald[warp * 4 + h];
    float wd[8];
#pragma unroll
    for (int d = 0; d < 8; d++) wd[d] = sw[d * 4 + h];

    // ---- pass A: alpha per (edge, head), running max ----
    float mx = -INFINITY;
    for (int p0 = beg; p0 < end; p0 += 8) {
        int myp = p0 + sub;
        float al = -INFINITY;
        if (myp < end) {
            int s = d_csrc[myp];
            const float4* ap = (const float4*)(d_ea_csr + (size_t)myp * 8);
            float4 e0 = ap[0], e1 = ap[1];
            float ale = e0.x * wd[0] + e0.y * wd[1] + e0.z * wd[2] + e0.w * wd[3]
                      + e1.x * wd[4] + e1.y * wd[5] + e1.z * wd[6] + e1.w * wd[7];
            float a = d_als[s * 4 + h] + ald_h + ale;
            al = a > 0.0f ? a : NEG * a;
            d_alpha[(size_t)myp * 4 + h] = al;   // warp offsets sub*4+h: coalesced 128B
        }
        mx = fmaxf(mx, al);
    }
#pragma unroll
    for (int off = 4; off; off >>= 1)
        mx = fmaxf(mx, __shfl_xor_sync(0xffffffffu, mx, off));  // max within 8-lane head group

    // ---- pass B: exp, denominator, weighted gather-aggregate ----
    float den = 0.0f, a0 = 0.0f, a1 = 0.0f;
    for (int p0 = beg; p0 < end; p0 += 8) {
        int myp = p0 + sub;
        float c = 0.0f;
        int s = 0;
        if (myp < end) {
            c = __expf(d_alpha[(size_t)myp * 4 + h] - mx);
            s = d_csrc[myp];
        }
        int nb = end - p0;
        if (nb >= 8) {
#pragma unroll
            for (int j = 0; j < 8; j++) {
                float cj = __shfl_sync(0xffffffffu, c, h * 8 + j);
                int   sj = __shfl_sync(0xffffffffu, s, j);
                float2 v = *(const float2*)(d_xp + (size_t)sj * 64 + lane * 2);
                den += cj; a0 += cj * v.x; a1 += cj * v.y;
            }
        } else {
            for (int j = 0; j < nb; j++) {
                float cj = __shfl_sync(0xffffffffu, c, h * 8 + j);
                int   sj = __shfl_sync(0xffffffffu, s, j);
                float2 v = *(const float2*)(d_xp + (size_t)sj * 64 + lane * 2);
                den += cj; a0 += cj * v.x; a1 += cj * v.y;
            }
        }
    }
    float inv = 1.0f / (den + 1e-16f);
    float o0 = a0 * inv + b[lane * 2];
    float o1 = a1 * inv + b[lane * 2 + 1];
    if (dorelu) { o0 = fmaxf(o0, 0.0f); o1 = fmaxf(o1, 0.0f); }
    *(float2*)(out + (size_t)warp * 64 + lane * 2) = make_float2(o0, o1);
}

// ---------------- global mean pool ----------------
__global__ void k_pool(const int* __restrict__ batch, const float* __restrict__ h) {
    size_t t = (size_t)blockIdx.x * blockDim.x + threadIdx.x;
    int n = (int)(t >> 5);
    if (n >= NN) return;
    int c2 = (int)(t & 31) * 2;
    int g = batch[n];
    red2(&d_pool[g * 64 + c2], h[(size_t)n * 64 + c2], h[(size_t)n * 64 + c2 + 1]);
    if (c2 == 0) atomicAdd(&d_gcnt[g], 1.0f);
}

// ---------------- MLP head ----------------
__global__ void k_mlp(const float* __restrict__ fc1w, const float* __restrict__ fc1b,
                      const float* __restrict__ fc2w, const float* __restrict__ fc2b,
                      float* __restrict__ out) {
    int g = threadIdx.x;
    if (g >= NGRAPH) return;
    float ic = 1.0f / fmaxf(d_gcnt[g], 1.0f);
    float hr[64];
#pragma unroll
    for (int c = 0; c < 64; c++) hr[c] = d_pool[g * 64 + c] * ic;
    float y1[32];
#pragma unroll
    for (int j = 0; j < 32; j++) {
        float s = fc1b[j];
#pragma unroll
        for (int c = 0; c < 64; c++) s += hr[c] * fc1w[c * 32 + j];
        y1[j] = fmaxf(s, 0.0f);
    }
#pragma unroll
    for (int o = 0; o < 2; o++) {
        float s = fc2b[o];
#pragma unroll
        for (int j = 0; j < 32; j++) s += y1[j] * fc2w[j * 2 + o];
        out[g * 2 + o] = s;
    }
}

// ---------------- host ----------------
extern "C" void kernel_launch(void* const* d_in, const int* in_sizes, int n_in,
                              void* d_out, int out_size) {
    (void)in_sizes; (void)n_in; (void)out_size;
    const float* x    = (const float*)d_in[0];
    const int*   ei   = (const int*)d_in[1];
    const float* ea   = (const float*)d_in[2];
    const int*   batch= (const int*)d_in[3];
    const float* W0   = (const float*)d_in[4];
    const float* as0  = (const float*)d_in[5];
    const float* ad0  = (const float*)d_in[6];
    const float* We0  = (const float*)d_in[7];
    const float* ae0  = (const float*)d_in[8];
    const float* b0   = (const float*)d_in[9];
    const float* Wh   = (const float*)d_in[10];
    const float* ash  = (const float*)d_in[11];
    const float* adh  = (const float*)d_in[12];
    const float* Weh  = (const float*)d_in[13];
    const float* aeh  = (const float*)d_in[14];
    const float* bh   = (const float*)d_in[15];
    const float* fc1w = (const float*)d_in[16];
    const float* fc1b = (const float*)d_in[17];
    const float* fc2w = (const float*)d_in[18];
    const float* fc2b = (const float*)d_in[19];
    float* out = (float*)d_out;

    const int* src = ei;
    const int* dst = ei + NE;

    void *p_cnt, *p_mean, *p_h0, *p_h1, *p_pool, *p_gcnt, *p_weatt;
    cudaGetSymbolAddress(&p_cnt,  d_cnt);
    cudaGetSymbolAddress(&p_mean, d_mean);
    cudaGetSymbolAddress(&p_h0,   d_h0);
    cudaGetSymbolAddress(&p_h1,   d_h1);
    cudaGetSymbolAddress(&p_pool, d_pool);
    cudaGetSymbolAddress(&p_gcnt, d_gcnt);
    cudaGetSymbolAddress(&p_weatt,d_weatt);

    // setup: degree count + self-loop mean attrs + CSR build (shared across layers)
    cudaMemsetAsync(p_cnt, 0, NN * sizeof(float));
    cudaMemsetAsync(p_mean, 0, NN * 8 * sizeof(float));
    k_count<<<(NE + 255) / 256, 256>>>(dst, ea);
    k_meandiv<<<(NN * 8 + 255) / 256, 256>>>();
    k_scan<<<1, 1024>>>();
    k_fill<<<(ESL + 255) / 256, 256>>>(src, dst, ea);
    k_weatt<<<1, 96>>>(We0, ae0, Weh, aeh);

    struct LayerCfg {
        const float* X; int fin; const float* W;
        const float* as; const float* ad; const float* b; float* hout; int relu;
    };
    LayerCfg L[3] = {
        { x,            32, W0,        as0,      ad0,      b0,      (float*)p_h0, 1 },
        { (float*)p_h0, 64, Wh,        ash,      adh,      bh,      (float*)p_h1, 0 },
        { (float*)p_h1, 64, Wh + 4096, ash + 64, adh + 64, bh + 64, (float*)p_h0, 0 },
    };

    for (int l = 0; l < 3; l++) {
        k_project<<<1184, 256>>>(L[l].X, L[l].fin, L[l].W, L[l].as, L[l].ad);
        k_agg<<<(NN * 32 + 255) / 256, 256>>>((const float*)p_weatt + l * 32,
                                              L[l].b, L[l].relu, L[l].hout);
    }

    cudaMemsetAsync(p_pool, 0, NGRAPH * 64 * sizeof(float));
    cudaMemsetAsync(p_gcnt, 0, NGRAPH * sizeof(float));
    k_pool<<<(int)(((size_t)NN * 32 + 255) / 256), 256>>>(batch, (const float*)p_h0);
    k_mlp<<<1, 64>>>(fc1w, fc1b, fc2w, fc2b, out);
}